// round 14
// baseline (speedup 1.0000x reference)
#include <cuda_runtime.h>
#include <cuda_bf16.h>
#include <math.h>
#include <stdint.h>

// Problem constants
#define BB   256
#define TT   512
#define DD   1024
#define HH   1024
#define MTOT (BB * TT)
#define BH   (BB * HH)
#define WSTRIDE (DD + HH)

// ---------------------------------------------------------------------------
// Scratch (device globals: allocation-free rule)
// ---------------------------------------------------------------------------
__device__ float g_xproj[134217728];             // [T][B][H]  512 MB
__device__ unsigned g_barM[4 * 32];              // 4 band barrier counters
__device__ unsigned short g_hh[2][BH];           // h hi bf16, parity buffered
__device__ unsigned short g_hl[2][BH];           // h lo bf16
__device__ unsigned short g_whh[1024 * 1024];    // Wh hi bf16 [n][k]
__device__ unsigned short g_whl[1024 * 1024];    // Wh lo bf16 [n][k]
__device__ unsigned short g_wxh[1024 * 1024];    // Wx hi bf16 [n][k]
__device__ unsigned short g_wxl[1024 * 1024];    // Wx lo bf16 [n][k]
__device__ unsigned short g_xh[134217728];       // xs hi bf16 [MTOT][D] 256 MB
__device__ unsigned short g_xl[134217728];       // xs lo bf16 [MTOT][D] 256 MB

// ---- mma.sync / ldmatrix / cp.async helpers (baseline sm_80+ ISA) ---------
__device__ __forceinline__ uint32_t smem_u32(const void* p) {
    uint32_t a;
    asm("{ .reg .u64 t; cvta.to.shared.u64 t, %1; cvt.u32.u64 %0, t; }" : "=r"(a) : "l"(p));
    return a;
}
__device__ __forceinline__ void ldsm4(uint32_t& r0, uint32_t& r1, uint32_t& r2,
                                      uint32_t& r3, uint32_t addr) {
    asm volatile("ldmatrix.sync.aligned.m8n8.x4.shared.b16 {%0,%1,%2,%3}, [%4];"
                 : "=r"(r0), "=r"(r1), "=r"(r2), "=r"(r3) : "r"(addr));
}
__device__ __forceinline__ void mma16816(float* c, uint32_t a0, uint32_t a1,
                                         uint32_t a2, uint32_t a3,
                                         uint32_t b0, uint32_t b1) {
    asm volatile("mma.sync.aligned.m16n8k16.row.col.f32.bf16.bf16.f32 "
                 "{%0,%1,%2,%3}, {%4,%5,%6,%7}, {%8,%9}, {%0,%1,%2,%3};"
                 : "+f"(c[0]), "+f"(c[1]), "+f"(c[2]), "+f"(c[3])
                 : "r"(a0), "r"(a1), "r"(a2), "r"(a3), "r"(b0), "r"(b1));
}
__device__ __forceinline__ void cpa16(uint32_t dst, const void* src) {
    size_t g = __cvta_generic_to_global(src);
    asm volatile("cp.async.cg.shared.global [%0], [%1], 16;" :: "r"(dst), "l"(g) : "memory");
}
#define CPA_COMMIT() asm volatile("cp.async.commit_group;" ::: "memory")
#define CPA_WAIT(n)  asm volatile("cp.async.wait_group %0;" :: "n"(n) : "memory")

__device__ __forceinline__ unsigned short bfbits(__nv_bfloat16 h) {
    return *reinterpret_cast<unsigned short*>(&h);
}
__device__ __forceinline__ unsigned pack_hi(float a, float b) {
    __nv_bfloat16 h0 = __float2bfloat16(a), h1 = __float2bfloat16(b);
    return (unsigned)bfbits(h0) | ((unsigned)bfbits(h1) << 16);
}
__device__ __forceinline__ unsigned pack_lo(float a, float b) {
    __nv_bfloat16 h0 = __float2bfloat16(a), h1 = __float2bfloat16(b);
    __nv_bfloat16 l0 = __float2bfloat16(a - __bfloat162float(h0));
    __nv_bfloat16 l1 = __float2bfloat16(b - __bfloat162float(h1));
    return (unsigned)bfbits(l0) | ((unsigned)bfbits(l1) << 16);
}

// ---------------------------------------------------------------------------
// Prep kernels: split xs / Wx / Wh into bf16 hi+lo
// ---------------------------------------------------------------------------
__global__ void __launch_bounds__(256) xsplit(const float* __restrict__ xs) {
    size_t i4 = ((size_t)blockIdx.x * 256 + threadIdx.x) * 4;
    float4 v = *reinterpret_cast<const float4*>(xs + i4);
    *reinterpret_cast<uint2*>(g_xh + i4) =
        make_uint2(pack_hi(v.x, v.y), pack_hi(v.z, v.w));
    *reinterpret_cast<uint2*>(g_xl + i4) =
        make_uint2(pack_lo(v.x, v.y), pack_lo(v.z, v.w));
}
__global__ void __launch_bounds__(256) w_prep(const float* __restrict__ W) {
    int idx = blockIdx.x * 256 + threadIdx.x;       // 0 .. 2^20-1
    int n = idx >> 10, k = idx & 1023;
    float wx = W[(size_t)n * WSTRIDE + k];
    __nv_bfloat16 xh = __float2bfloat16(wx);
    g_wxh[idx] = bfbits(xh);
    g_wxl[idx] = bfbits(__float2bfloat16(wx - __bfloat162float(xh)));
    float wh = W[(size_t)n * WSTRIDE + DD + k];
    __nv_bfloat16 hh = __float2bfloat16(wh);
    g_whh[idx] = bfbits(hh);
    g_whl[idx] = bfbits(__float2bfloat16(wh - __bfloat162float(hh)));
}

// ---------------------------------------------------------------------------
// Kernel 1: x_proj HMMA GEMM v2 (unchanged from round 13, proven).
// ---------------------------------------------------------------------------
#define XS 72
#define X_RA (128 * XS * 2)
#define X_ABUF (2 * X_RA)
#define X_ATOT (2 * X_ABUF)
#define X_RB (128 * XS * 2)
#define X_BBUF (2 * X_RB)
#define XP2_SMEM (X_ATOT + 2 * X_BBUF)         // 147456 B

__device__ __forceinline__ void xstage(uint32_t sb, int buf, int gm0, int n0,
                                       int kc, int tid) {
#pragma unroll
    for (int q = 0; q < 4; q++) {
        int i = tid + q * 256;
        int row = i >> 3, ko = (i & 7) * 8;
        size_t asrc = (size_t)(gm0 + row) * 1024 + kc + ko;
        uint32_t adst = sb + buf * X_ABUF + (uint32_t)((row * XS + ko) * 2);
        cpa16(adst, g_xh + asrc);
        cpa16(adst + X_RA, g_xl + asrc);
        size_t bsrc = (size_t)(n0 + row) * 1024 + kc + ko;
        uint32_t bdst = sb + X_ATOT + buf * X_BBUF + (uint32_t)((row * XS + ko) * 2);
        cpa16(bdst, g_wxh + bsrc);
        cpa16(bdst + X_RB, g_wxl + bsrc);
    }
}

__global__ void __launch_bounds__(256, 1)
xproj_hmma(const float* __restrict__ bias) {
    extern __shared__ __align__(16) char smem[];
    const uint32_t sb = smem_u32(smem);
    const int tid  = threadIdx.x;
    const int wid  = tid >> 5;
    const int lane = tid & 31;
    const int n0  = blockIdx.x * 128;
    const int gm0 = blockIdx.y * 128;
    const int wm = wid >> 2;
    const int wn = wid & 3;
    const int gid = lane >> 2, tig = lane & 3;

    uint32_t a_off[4], b_off[2];
#pragma unroll
    for (int mt = 0; mt < 4; mt++)
        a_off[mt] = (uint32_t)(((wm * 64 + mt * 16 + (lane & 7) + ((lane >> 3) & 1) * 8) * XS
                                + (lane >> 4) * 8) * 2);
#pragma unroll
    for (int nt = 0; nt < 2; nt++)
        b_off[nt] = (uint32_t)(((wn * 32 + nt * 16 + (lane & 7) + (lane >> 4) * 8) * XS
                                + ((lane >> 3) & 1) * 8) * 2);

    float acc[4][4][4];
#pragma unroll
    for (int i = 0; i < 4; i++)
#pragma unroll
        for (int j = 0; j < 4; j++)
#pragma unroll
            for (int q = 0; q < 4; q++) acc[i][j][q] = 0.0f;

    xstage(sb, 0, gm0, n0, 0, tid);  CPA_COMMIT();
    xstage(sb, 1, gm0, n0, 64, tid); CPA_COMMIT();

#pragma unroll 1
    for (int c = 0; c < 16; c++) {
        CPA_WAIT(1);
        __syncthreads();

        const uint32_t ab = sb + (c & 1) * X_ABUF;
        const uint32_t bb = sb + X_ATOT + (c & 1) * X_BBUF;
#pragma unroll
        for (int ks = 0; ks < 4; ks++) {
            uint32_t AH[4][4], AL[4][4];
#pragma unroll
            for (int mt = 0; mt < 4; mt++) {
                ldsm4(AH[mt][0], AH[mt][1], AH[mt][2], AH[mt][3], ab + a_off[mt] + ks * 32);
                ldsm4(AL[mt][0], AL[mt][1], AL[mt][2], AL[mt][3],
                      ab + X_RA + a_off[mt] + ks * 32);
            }
#pragma unroll
            for (int nt = 0; nt < 2; nt++) {
                uint32_t bh0, bh1, bh2, bh3, bl0, bl1, bl2, bl3;
                ldsm4(bh0, bh1, bh2, bh3, bb + b_off[nt] + ks * 32);
                ldsm4(bl0, bl1, bl2, bl3, bb + X_RB + b_off[nt] + ks * 32);
#pragma unroll
                for (int mt = 0; mt < 4; mt++) {
                    mma16816(acc[mt][nt * 2 + 0], AH[mt][0], AH[mt][1], AH[mt][2], AH[mt][3], bh0, bh1);
                    mma16816(acc[mt][nt * 2 + 1], AH[mt][0], AH[mt][1], AH[mt][2], AH[mt][3], bh2, bh3);
                    mma16816(acc[mt][nt * 2 + 0], AH[mt][0], AH[mt][1], AH[mt][2], AH[mt][3], bl0, bl1);
                    mma16816(acc[mt][nt * 2 + 1], AH[mt][0], AH[mt][1], AH[mt][2], AH[mt][3], bl2, bl3);
                    mma16816(acc[mt][nt * 2 + 0], AL[mt][0], AL[mt][1], AL[mt][2], AL[mt][3], bh0, bh1);
                    mma16816(acc[mt][nt * 2 + 1], AL[mt][0], AL[mt][1], AL[mt][2], AL[mt][3], bh2, bh3);
                }
            }
        }
        __syncthreads();
        if (c + 2 < 16) xstage(sb, c & 1, gm0, n0, (c + 2) * 64, tid);
        CPA_COMMIT();
    }

    float2 bias2[4];
#pragma unroll
    for (int nq = 0; nq < 4; nq++) {
        int cn = n0 + wn * 32 + (nq >> 1) * 16 + (nq & 1) * 8 + tig * 2;
        bias2[nq] = *reinterpret_cast<const float2*>(bias + cn);
    }
#pragma unroll
    for (int mt = 0; mt < 4; mt++) {
#pragma unroll
        for (int half = 0; half < 2; half++) {
            int gm = gm0 + wm * 64 + mt * 16 + gid + half * 8;
            int b_idx = gm >> 9, tq = gm & 511;
            float* orow = g_xproj + ((size_t)tq * BB + b_idx) * HH;
#pragma unroll
            for (int nq = 0; nq < 4; nq++) {
                int cn = n0 + wn * 32 + (nq >> 1) * 16 + (nq & 1) * 8 + tig * 2;
                *reinterpret_cast<float2*>(orow + cn) =
                    make_float2(acc[mt][nq][half * 2 + 0] + bias2[nq].x,
                                acc[mt][nq][half * 2 + 1] + bias2[nq].y);
            }
        }
    }
}

// ---------------------------------------------------------------------------
// Kernel 2: persistent HMMA recurrence v3.
// Grid (32 ni, 4 mi) = 128 CTAs, 256 threads = 4 k-groups x 2 m-warps.
// Warp tile 32m x 32n, k range [wg*256,+256) in 8 chunks of 32; per-group
// double-buffered cp.async A staging; 4-way k-reduction through smem;
// epilogue spread over all 256 threads (uint4 h stores).
// ---------------------------------------------------------------------------
#define RB_STRIDE 1032
#define RB_SIZE   (32 * RB_STRIDE * 2)      // 66048 B
#define RA2_STRIDE 40                       // 32k + 8 pad (elems)
#define RA2_SIZE  (64 * RA2_STRIDE * 2)     // 5120 B per array
#define A2_BUFSZ  (2 * RA2_SIZE)            // hi+lo = 10240
#define A2_GRP    (2 * A2_BUFSZ)            // 2 bufs = 20480
#define A2_OFF    (2 * RB_SIZE)             // 132096
#define RED_STRIDE 36                       // fp32 elems per reduction row
#define RED_GRP   (64 * RED_STRIDE * 4)     // 9216 B (fits in A2 region)
#define XP_OFF    (A2_OFF + 4 * A2_GRP)     // 214016
#define XP_STRIDE 36
#define RC_SMEM   (XP_OFF + 64 * XP_STRIDE * 4)   // 223232 B

__global__ void __launch_bounds__(256, 1)
recur_hmma(float* __restrict__ out, int copies) {
    extern __shared__ __align__(16) char smem[];
    const uint32_t sb = smem_u32(smem);
    const int tid  = threadIdx.x;
    const int wid  = tid >> 5;
    const int lane = tid & 31;
    const int ni = blockIdx.x;              // 0..31
    const int mi = blockIdx.y;              // 0..3
    const int m0 = mi * 64;
    const int n0 = ni * 32;
    const int wg = wid >> 1;                // k-group 0..3
    const int wm = wid & 1;                 // m half 0..1
    const int gt = tid & 63;                // thread-in-group
    unsigned* ctr = &g_barM[mi * 32];

    // ---- stage resident Wh slice (rows [n0,+32), hi/lo) -------------------
#pragma unroll
    for (int q = 0; q < 16; q++) {
        int i = tid + q * 256;
        int row = i >> 7, ko = (i & 127) * 8;
        size_t src = (size_t)(n0 + row) * 1024 + ko;
        uint4 vh = *reinterpret_cast<const uint4*>(g_whh + src);
        *reinterpret_cast<uint4*>(smem + (row * RB_STRIDE + ko) * 2) = vh;
        uint4 vl = *reinterpret_cast<const uint4*>(g_whl + src);
        *reinterpret_cast<uint4*>(smem + RB_SIZE + (row * RB_STRIDE + ko) * 2) = vl;
    }

    // ---- Step 0: h0 = 0 -> h[0] = split(tanh(x_proj[0])) on own tile ------
#pragma unroll
    for (int q = 0; q < 2; q++) {
        int i = tid + q * 256;
        int row = i >> 3, c4 = (i & 7) * 4;
        size_t off = (size_t)(m0 + row) * HH + n0 + c4;
        float4 v = __ldcs(reinterpret_cast<const float4*>(g_xproj + off));
        float o[4] = {tanhf(v.x), tanhf(v.y), tanhf(v.z), tanhf(v.w)};
        *reinterpret_cast<uint2*>(&g_hh[0][off]) =
            make_uint2(pack_hi(o[0], o[1]), pack_hi(o[2], o[3]));
        *reinterpret_cast<uint2*>(&g_hl[0][off]) =
            make_uint2(pack_lo(o[0], o[1]), pack_lo(o[2], o[3]));
    }

    // per-lane ldmatrix addresses
    const int frow = (lane & 7) + ((lane >> 3) & 1) * 8;   // A row-in-16-tile
    const int fk8  = (lane >> 4) * 8;                      // A k8
    uint32_t a_off[2];
#pragma unroll
    for (int mt = 0; mt < 2; mt++)
        a_off[mt] = (uint32_t)(((wm * 32 + mt * 16 + frow) * RA2_STRIDE + fk8) * 2);
    const int brow = (lane & 7) + (lane >> 4) * 8;         // B row-in-16-tile
    const int bk8  = ((lane >> 3) & 1) * 8;
    uint32_t b_off[2];
#pragma unroll
    for (int nt = 0; nt < 2; nt++)
        b_off[nt] = (uint32_t)(((nt * 16 + brow) * RB_STRIDE + bk8) * 2);

    const uint32_t ag_base = sb + A2_OFF + wg * A2_GRP;
    const int kg = wg * 256;                               // group k base

    // A-staging mapping: 256 slots (row 0..63, 4x 8-elem segments)
    const int s_row = gt >> 2;   // first of 16 rows handled via j loop below
    // (each thread handles slots gt, gt+64, gt+128, gt+192)

    for (int t = 1; t < TT; t++) {
        // band barrier over 32 CTAs (monotone counter, bounded spin)
        __syncthreads();
        if (tid == 0) {
            __threadfence();
            atomicAdd(ctr, 1u);
            unsigned tgt = (unsigned)t * 32u;
            for (int it = 0; it < (1 << 18); ++it) {
                if (*((volatile unsigned*)ctr) >= tgt) break;
                __nanosleep(64);
            }
            __threadfence();
        }
        __syncthreads();

        const int par = (t - 1) & 1;
        const unsigned short* sh = g_hh[par];
        const unsigned short* sl = g_hl[par];

        float acc[2][4][4];
#pragma unroll
        for (int i = 0; i < 2; i++)
#pragma unroll
            for (int j = 0; j < 4; j++)
#pragma unroll
                for (int q = 0; q < 4; q++) acc[i][j][q] = 0.0f;

        // xp prefetch (64m x 32n fp32) rides in the first commit group
        {
            const float* xpt = g_xproj + (size_t)t * BH;
#pragma unroll
            for (int q = 0; q < 2; q++) {
                int i = tid + q * 256;
                int row = i >> 3, c4 = (i & 7) * 4;
                cpa16(sb + XP_OFF + (uint32_t)((row * XP_STRIDE + c4) * 4),
                      xpt + (size_t)(m0 + row) * HH + n0 + c4);
            }
        }
        // prologue: stage this group's chunks 0,1
#pragma unroll
        for (int pc = 0; pc < 2; pc++) {
            uint32_t ab = ag_base + pc * A2_BUFSZ;
            int kbase = kg + pc * 32;
#pragma unroll
            for (int j = 0; j < 4; j++) {
                int i = gt + j * 64;
                int row = i >> 2, ko = (i & 3) * 8;
                size_t src = (size_t)(m0 + row) * HH + kbase + ko;
                uint32_t dst = ab + (uint32_t)((row * RA2_STRIDE + ko) * 2);
                cpa16(dst, sh + src);
                cpa16(dst + RA2_SIZE, sl + src);
            }
            CPA_COMMIT();
        }

#pragma unroll 1
        for (int c = 0; c < 8; c++) {
            CPA_WAIT(1);
            __syncthreads();

            const uint32_t ab = ag_base + (c & 1) * A2_BUFSZ;
            const uint32_t bkofs = (uint32_t)((kg + c * 32) * 2);
#pragma unroll
            for (int ks = 0; ks < 2; ks++) {
                uint32_t AH[2][4], AL[2][4];
#pragma unroll
                for (int mt = 0; mt < 2; mt++) {
                    ldsm4(AH[mt][0], AH[mt][1], AH[mt][2], AH[mt][3],
                          ab + a_off[mt] + ks * 32);
                    ldsm4(AL[mt][0], AL[mt][1], AL[mt][2], AL[mt][3],
                          ab + RA2_SIZE + a_off[mt] + ks * 32);
                }
#pragma unroll
                for (int nt = 0; nt < 2; nt++) {
                    uint32_t bh0, bh1, bh2, bh3, bl0, bl1, bl2, bl3;
                    ldsm4(bh0, bh1, bh2, bh3, sb + b_off[nt] + bkofs + ks * 32);
                    ldsm4(bl0, bl1, bl2, bl3, sb + RB_SIZE + b_off[nt] + bkofs + ks * 32);
#pragma unroll
                    for (int mt = 0; mt < 2; mt++) {
                        mma16816(acc[mt][nt * 2 + 0], AH[mt][0], AH[mt][1], AH[mt][2], AH[mt][3], bh0, bh1);
                        mma16816(acc[mt][nt * 2 + 1], AH[mt][0], AH[mt][1], AH[mt][2], AH[mt][3], bh2, bh3);
                        mma16816(acc[mt][nt * 2 + 0], AH[mt][0], AH[mt][1], AH[mt][2], AH[mt][3], bl0, bl1);
                        mma16816(acc[mt][nt * 2 + 1], AH[mt][0], AH[mt][1], AH[mt][2], AH[mt][3], bl2, bl3);
                        mma16816(acc[mt][nt * 2 + 0], AL[mt][0], AL[mt][1], AL[mt][2], AL[mt][3], bh0, bh1);
                        mma16816(acc[mt][nt * 2 + 1], AL[mt][0], AL[mt][1], AL[mt][2], AL[mt][3], bh2, bh3);
                    }
                }
            }
            __syncthreads();                 // reads done before restage
            if (c + 2 < 8) {
                uint32_t abn = ag_base + (c & 1) * A2_BUFSZ;
                int kbase = kg + (c + 2) * 32;
#pragma unroll
                for (int j = 0; j < 4; j++) {
                    int i = gt + j * 64;
                    int row = i >> 2, ko = (i & 3) * 8;
                    size_t src = (size_t)(m0 + row) * HH + kbase + ko;
                    uint32_t dst = abn + (uint32_t)((row * RA2_STRIDE + ko) * 2);
                    cpa16(dst, sh + src);
                    cpa16(dst + RA2_SIZE, sl + src);
                }
            }
            CPA_COMMIT();
        }

        // ---- 4-way k-reduction via smem (reuses A2 region) ----------------
        __syncthreads();                     // all A-buffer reads complete
        {
            float* red = reinterpret_cast<float*>(smem + A2_OFF + wg * RED_GRP);
            const int gid = lane >> 2, tig = lane & 3;
#pragma unroll
            for (int mt = 0; mt < 2; mt++)
#pragma unroll
                for (int half = 0; half < 2; half++) {
                    int row = wm * 32 + mt * 16 + gid + half * 8;
#pragma unroll
                    for (int nq = 0; nq < 4; nq++) {
                        int col = nq * 8 + tig * 2;
                        *reinterpret_cast<float2*>(&red[row * RED_STRIDE + col]) =
                            make_float2(acc[mt][nq][half * 2 + 0],
                                        acc[mt][nq][half * 2 + 1]);
                    }
                }
        }
        __syncthreads();

        // ---- epilogue: sum 4 groups + xp -> tanh -> split -> h (or out) ---
        {
            const int row = tid >> 2;               // 0..63
            const int cb  = (tid & 3) * 8;          // 0,8,16,24
            const float* redb = reinterpret_cast<const float*>(smem + A2_OFF);
            float s[8];
            {
                const float* xp = reinterpret_cast<const float*>(
                    smem + XP_OFF) + row * XP_STRIDE + cb;
#pragma unroll
                for (int q = 0; q < 8; q++) s[q] = xp[q];
            }
#pragma unroll
            for (int g = 0; g < 4; g++) {
                const float* r = redb + g * (RED_GRP / 4) + row * RED_STRIDE + cb;
#pragma unroll
                for (int q = 0; q < 8; q++) s[q] += r[q];
            }
            float o[8];
#pragma unroll
            for (int q = 0; q < 8; q++) o[q] = tanhf(s[q]);
            const size_t off = (size_t)(m0 + row) * HH + n0 + cb;
            if (t == TT - 1) {
                for (int cc = 0; cc < copies; cc++) {
                    float4* op = reinterpret_cast<float4*>(out + (size_t)cc * BH + off);
                    op[0] = make_float4(o[0], o[1], o[2], o[3]);
                    op[1] = make_float4(o[4], o[5], o[6], o[7]);
                }
            } else {
                const int wpar = t & 1;
                *reinterpret_cast<uint4*>(&g_hh[wpar][off]) =
                    make_uint4(pack_hi(o[0], o[1]), pack_hi(o[2], o[3]),
                               pack_hi(o[4], o[5]), pack_hi(o[6], o[7]));
                *reinterpret_cast<uint4*>(&g_hl[wpar][off]) =
                    make_uint4(pack_lo(o[0], o[1]), pack_lo(o[2], o[3]),
                               pack_lo(o[4], o[5]), pack_lo(o[6], o[7]));
            }
        }
    }

    // ---- exit: band-local barrier + protected, bounded counter reset ------
    __syncthreads();
    if (tid == 0) {
        __threadfence();
        atomicAdd(ctr, 1u);
        if (ni == 0) {
            for (int it = 0; it < (1 << 20); ++it) {
                if (*((volatile unsigned*)ctr) >= (unsigned)TT * 32u) break;
                __nanosleep(64);
            }
            atomicExch(ctr, 0u);
        }
    }
}

// ---------------------------------------------------------------------------
extern "C" void kernel_launch(void* const* d_in, const int* in_sizes, int n_in,
                              void* d_out, int out_size) {
    const float* xs = nullptr; const float* W = nullptr; const float* b = nullptr;
    for (int i = 0; i < n_in; i++) {
        if (in_sizes[i] == MTOT * DD)            xs = (const float*)d_in[i];
        else if (in_sizes[i] == HH * WSTRIDE)    W  = (const float*)d_in[i];
        else if (in_sizes[i] == HH)              b  = (const float*)d_in[i];
    }
    float* out = (float*)d_out;
    int copies = out_size / BH;
    if (copies < 1) copies = 1;
    if (copies > 2) copies = 2;

    static bool configured = false;
    if (!configured) {
        cudaFuncSetAttribute(xproj_hmma,
                             cudaFuncAttributeMaxDynamicSharedMemorySize, XP2_SMEM);
        cudaFuncSetAttribute(recur_hmma,
                             cudaFuncAttributeMaxDynamicSharedMemorySize, RC_SMEM);
        configured = true;
    }

    xsplit<<<131072, 256>>>(xs);
    w_prep<<<4096, 256>>>(W);
    xproj_hmma<<<dim3(8, 1024), 256, XP2_SMEM>>>(b);
    recur_hmma<<<dim3(32, 4), 256, RC_SMEM>>>(out, copies);
}

// round 15
// speedup vs baseline: 1.1336x; 1.1336x over previous
#include <cuda_runtime.h>
#include <cuda_bf16.h>
#include <math.h>
#include <stdint.h>

// Problem constants
#define BB   256
#define TT   512
#define DD   1024
#define HH   1024
#define MTOT (BB * TT)
#define BH   (BB * HH)
#define WSTRIDE (DD + HH)

// ---------------------------------------------------------------------------
// Scratch (device globals: allocation-free rule)
// ---------------------------------------------------------------------------
__device__ float g_xproj[134217728];             // [T][B][H]  512 MB
__device__ unsigned g_barM[4 * 32];              // 4 band barrier counters
__device__ unsigned short g_hh[2][BH];           // h hi bf16, parity buffered
__device__ unsigned short g_hl[2][BH];           // h lo bf16
__device__ unsigned short g_whh[1024 * 1024];    // Wh hi bf16 [n][k]
__device__ unsigned short g_whl[1024 * 1024];    // Wh lo bf16 [n][k]
__device__ unsigned short g_wxh[1024 * 1024];    // Wx hi bf16 [n][k]
__device__ unsigned short g_wxl[1024 * 1024];    // Wx lo bf16 [n][k]
__device__ unsigned short g_xh[134217728];       // xs hi bf16 [MTOT][D] 256 MB
__device__ unsigned short g_xl[134217728];       // xs lo bf16 [MTOT][D] 256 MB

// ---- mma.sync / ldmatrix / cp.async helpers (baseline sm_80+ ISA) ---------
__device__ __forceinline__ uint32_t smem_u32(const void* p) {
    uint32_t a;
    asm("{ .reg .u64 t; cvta.to.shared.u64 t, %1; cvt.u32.u64 %0, t; }" : "=r"(a) : "l"(p));
    return a;
}
__device__ __forceinline__ void ldsm4(uint32_t& r0, uint32_t& r1, uint32_t& r2,
                                      uint32_t& r3, uint32_t addr) {
    asm volatile("ldmatrix.sync.aligned.m8n8.x4.shared.b16 {%0,%1,%2,%3}, [%4];"
                 : "=r"(r0), "=r"(r1), "=r"(r2), "=r"(r3) : "r"(addr));
}
__device__ __forceinline__ void mma16816(float* c, uint32_t a0, uint32_t a1,
                                         uint32_t a2, uint32_t a3,
                                         uint32_t b0, uint32_t b1) {
    asm volatile("mma.sync.aligned.m16n8k16.row.col.f32.bf16.bf16.f32 "
                 "{%0,%1,%2,%3}, {%4,%5,%6,%7}, {%8,%9}, {%0,%1,%2,%3};"
                 : "+f"(c[0]), "+f"(c[1]), "+f"(c[2]), "+f"(c[3])
                 : "r"(a0), "r"(a1), "r"(a2), "r"(a3), "r"(b0), "r"(b1));
}
__device__ __forceinline__ void cpa16(uint32_t dst, const void* src) {
    size_t g = __cvta_generic_to_global(src);
    asm volatile("cp.async.cg.shared.global [%0], [%1], 16;" :: "r"(dst), "l"(g) : "memory");
}
#define CPA_COMMIT() asm volatile("cp.async.commit_group;" ::: "memory")
#define CPA_WAIT(n)  asm volatile("cp.async.wait_group %0;" :: "n"(n) : "memory")
#define BAR_GRP(id)  asm volatile("bar.sync %0, 64;" :: "r"(id) : "memory")

__device__ __forceinline__ void atom_add_release(unsigned* p, unsigned v) {
    unsigned old;
    asm volatile("atom.add.release.gpu.u32 %0, [%1], %2;"
                 : "=r"(old) : "l"(p), "r"(v) : "memory");
}
__device__ __forceinline__ unsigned ld_acquire(unsigned* p) {
    unsigned v;
    asm volatile("ld.acquire.gpu.u32 %0, [%1];" : "=r"(v) : "l"(p) : "memory");
    return v;
}

__device__ __forceinline__ unsigned short bfbits(__nv_bfloat16 h) {
    return *reinterpret_cast<unsigned short*>(&h);
}
__device__ __forceinline__ unsigned pack_hi(float a, float b) {
    __nv_bfloat16 h0 = __float2bfloat16(a), h1 = __float2bfloat16(b);
    return (unsigned)bfbits(h0) | ((unsigned)bfbits(h1) << 16);
}
__device__ __forceinline__ unsigned pack_lo(float a, float b) {
    __nv_bfloat16 h0 = __float2bfloat16(a), h1 = __float2bfloat16(b);
    __nv_bfloat16 l0 = __float2bfloat16(a - __bfloat162float(h0));
    __nv_bfloat16 l1 = __float2bfloat16(b - __bfloat162float(h1));
    return (unsigned)bfbits(l0) | ((unsigned)bfbits(l1) << 16);
}

// ---------------------------------------------------------------------------
// Prep kernels: split xs / Wx / Wh into bf16 hi+lo
// ---------------------------------------------------------------------------
__global__ void __launch_bounds__(256) xsplit(const float* __restrict__ xs) {
    size_t i4 = ((size_t)blockIdx.x * 256 + threadIdx.x) * 4;
    float4 v = *reinterpret_cast<const float4*>(xs + i4);
    *reinterpret_cast<uint2*>(g_xh + i4) =
        make_uint2(pack_hi(v.x, v.y), pack_hi(v.z, v.w));
    *reinterpret_cast<uint2*>(g_xl + i4) =
        make_uint2(pack_lo(v.x, v.y), pack_lo(v.z, v.w));
}
__global__ void __launch_bounds__(256) w_prep(const float* __restrict__ W) {
    int idx = blockIdx.x * 256 + threadIdx.x;       // 0 .. 2^20-1
    int n = idx >> 10, k = idx & 1023;
    float wx = W[(size_t)n * WSTRIDE + k];
    __nv_bfloat16 xh = __float2bfloat16(wx);
    g_wxh[idx] = bfbits(xh);
    g_wxl[idx] = bfbits(__float2bfloat16(wx - __bfloat162float(xh)));
    float wh = W[(size_t)n * WSTRIDE + DD + k];
    __nv_bfloat16 hh = __float2bfloat16(wh);
    g_whh[idx] = bfbits(hh);
    g_whl[idx] = bfbits(__float2bfloat16(wh - __bfloat162float(hh)));
}

// ---------------------------------------------------------------------------
// Kernel 1: x_proj HMMA GEMM v2 (unchanged, proven).
// ---------------------------------------------------------------------------
#define XS 72
#define X_RA (128 * XS * 2)
#define X_ABUF (2 * X_RA)
#define X_ATOT (2 * X_ABUF)
#define X_RB (128 * XS * 2)
#define X_BBUF (2 * X_RB)
#define XP2_SMEM (X_ATOT + 2 * X_BBUF)         // 147456 B

__device__ __forceinline__ void xstage(uint32_t sb, int buf, int gm0, int n0,
                                       int kc, int tid) {
#pragma unroll
    for (int q = 0; q < 4; q++) {
        int i = tid + q * 256;
        int row = i >> 3, ko = (i & 7) * 8;
        size_t asrc = (size_t)(gm0 + row) * 1024 + kc + ko;
        uint32_t adst = sb + buf * X_ABUF + (uint32_t)((row * XS + ko) * 2);
        cpa16(adst, g_xh + asrc);
        cpa16(adst + X_RA, g_xl + asrc);
        size_t bsrc = (size_t)(n0 + row) * 1024 + kc + ko;
        uint32_t bdst = sb + X_ATOT + buf * X_BBUF + (uint32_t)((row * XS + ko) * 2);
        cpa16(bdst, g_wxh + bsrc);
        cpa16(bdst + X_RB, g_wxl + bsrc);
    }
}

__global__ void __launch_bounds__(256, 1)
xproj_hmma(const float* __restrict__ bias) {
    extern __shared__ __align__(16) char smem[];
    const uint32_t sb = smem_u32(smem);
    const int tid  = threadIdx.x;
    const int wid  = tid >> 5;
    const int lane = tid & 31;
    const int n0  = blockIdx.x * 128;
    const int gm0 = blockIdx.y * 128;
    const int wm = wid >> 2;
    const int wn = wid & 3;
    const int gid = lane >> 2, tig = lane & 3;

    uint32_t a_off[4], b_off[2];
#pragma unroll
    for (int mt = 0; mt < 4; mt++)
        a_off[mt] = (uint32_t)(((wm * 64 + mt * 16 + (lane & 7) + ((lane >> 3) & 1) * 8) * XS
                                + (lane >> 4) * 8) * 2);
#pragma unroll
    for (int nt = 0; nt < 2; nt++)
        b_off[nt] = (uint32_t)(((wn * 32 + nt * 16 + (lane & 7) + (lane >> 4) * 8) * XS
                                + ((lane >> 3) & 1) * 8) * 2);

    float acc[4][4][4];
#pragma unroll
    for (int i = 0; i < 4; i++)
#pragma unroll
        for (int j = 0; j < 4; j++)
#pragma unroll
            for (int q = 0; q < 4; q++) acc[i][j][q] = 0.0f;

    xstage(sb, 0, gm0, n0, 0, tid);  CPA_COMMIT();
    xstage(sb, 1, gm0, n0, 64, tid); CPA_COMMIT();

#pragma unroll 1
    for (int c = 0; c < 16; c++) {
        CPA_WAIT(1);
        __syncthreads();

        const uint32_t ab = sb + (c & 1) * X_ABUF;
        const uint32_t bb = sb + X_ATOT + (c & 1) * X_BBUF;
#pragma unroll
        for (int ks = 0; ks < 4; ks++) {
            uint32_t AH[4][4], AL[4][4];
#pragma unroll
            for (int mt = 0; mt < 4; mt++) {
                ldsm4(AH[mt][0], AH[mt][1], AH[mt][2], AH[mt][3], ab + a_off[mt] + ks * 32);
                ldsm4(AL[mt][0], AL[mt][1], AL[mt][2], AL[mt][3],
                      ab + X_RA + a_off[mt] + ks * 32);
            }
#pragma unroll
            for (int nt = 0; nt < 2; nt++) {
                uint32_t bh0, bh1, bh2, bh3, bl0, bl1, bl2, bl3;
                ldsm4(bh0, bh1, bh2, bh3, bb + b_off[nt] + ks * 32);
                ldsm4(bl0, bl1, bl2, bl3, bb + X_RB + b_off[nt] + ks * 32);
#pragma unroll
                for (int mt = 0; mt < 4; mt++) {
                    mma16816(acc[mt][nt * 2 + 0], AH[mt][0], AH[mt][1], AH[mt][2], AH[mt][3], bh0, bh1);
                    mma16816(acc[mt][nt * 2 + 1], AH[mt][0], AH[mt][1], AH[mt][2], AH[mt][3], bh2, bh3);
                    mma16816(acc[mt][nt * 2 + 0], AH[mt][0], AH[mt][1], AH[mt][2], AH[mt][3], bl0, bl1);
                    mma16816(acc[mt][nt * 2 + 1], AH[mt][0], AH[mt][1], AH[mt][2], AH[mt][3], bl2, bl3);
                    mma16816(acc[mt][nt * 2 + 0], AL[mt][0], AL[mt][1], AL[mt][2], AL[mt][3], bh0, bh1);
                    mma16816(acc[mt][nt * 2 + 1], AL[mt][0], AL[mt][1], AL[mt][2], AL[mt][3], bh2, bh3);
                }
            }
        }
        __syncthreads();
        if (c + 2 < 16) xstage(sb, c & 1, gm0, n0, (c + 2) * 64, tid);
        CPA_COMMIT();
    }

    float2 bias2[4];
#pragma unroll
    for (int nq = 0; nq < 4; nq++) {
        int cn = n0 + wn * 32 + (nq >> 1) * 16 + (nq & 1) * 8 + tig * 2;
        bias2[nq] = *reinterpret_cast<const float2*>(bias + cn);
    }
#pragma unroll
    for (int mt = 0; mt < 4; mt++) {
#pragma unroll
        for (int half = 0; half < 2; half++) {
            int gm = gm0 + wm * 64 + mt * 16 + gid + half * 8;
            int b_idx = gm >> 9, tq = gm & 511;
            float* orow = g_xproj + ((size_t)tq * BB + b_idx) * HH;
#pragma unroll
            for (int nq = 0; nq < 4; nq++) {
                int cn = n0 + wn * 32 + (nq >> 1) * 16 + (nq & 1) * 8 + tig * 2;
                *reinterpret_cast<float2*>(orow + cn) =
                    make_float2(acc[mt][nq][half * 2 + 0] + bias2[nq].x,
                                acc[mt][nq][half * 2 + 1] + bias2[nq].y);
            }
        }
    }
}

// ---------------------------------------------------------------------------
// Kernel 2: persistent HMMA recurrence v4 (latency-trimmed).
// Grid (32 ni, 4 mi) = 128 CTAs, 256 threads = 4 k-groups x 2 m-warps.
// Changes vs v3: release/acquire band barrier (no fence.sc), xp prefetch
// overlapped with the barrier spin, per-group named barriers in the chunk
// loop (groups fully decoupled), tight acquire polling.
// ---------------------------------------------------------------------------
#define RB_STRIDE 1032
#define RB_SIZE   (32 * RB_STRIDE * 2)      // 66048 B
#define RA2_STRIDE 40
#define RA2_SIZE  (64 * RA2_STRIDE * 2)     // 5120 B per array
#define A2_BUFSZ  (2 * RA2_SIZE)            // 10240
#define A2_GRP    (2 * A2_BUFSZ)            // 20480
#define A2_OFF    (2 * RB_SIZE)             // 132096
#define RED_STRIDE 36
#define RED_GRP   (64 * RED_STRIDE * 4)     // 9216 B
#define XP_OFF    (A2_OFF + 4 * A2_GRP)     // 214016
#define XP_STRIDE 36
#define RC_SMEM   (XP_OFF + 64 * XP_STRIDE * 4)   // 223232 B

__global__ void __launch_bounds__(256, 1)
recur_hmma(float* __restrict__ out, int copies) {
    extern __shared__ __align__(16) char smem[];
    const uint32_t sb = smem_u32(smem);
    const int tid  = threadIdx.x;
    const int wid  = tid >> 5;
    const int lane = tid & 31;
    const int ni = blockIdx.x;              // 0..31
    const int mi = blockIdx.y;              // 0..3
    const int m0 = mi * 64;
    const int n0 = ni * 32;
    const int wg = wid >> 1;                // k-group 0..3
    const int wm = wid & 1;                 // m half 0..1
    const int gt = tid & 63;                // thread-in-group
    unsigned* ctr = &g_barM[mi * 32];

    // ---- stage resident Wh slice (rows [n0,+32), hi/lo) -------------------
#pragma unroll
    for (int q = 0; q < 16; q++) {
        int i = tid + q * 256;
        int row = i >> 7, ko = (i & 127) * 8;
        size_t src = (size_t)(n0 + row) * 1024 + ko;
        uint4 vh = *reinterpret_cast<const uint4*>(g_whh + src);
        *reinterpret_cast<uint4*>(smem + (row * RB_STRIDE + ko) * 2) = vh;
        uint4 vl = *reinterpret_cast<const uint4*>(g_whl + src);
        *reinterpret_cast<uint4*>(smem + RB_SIZE + (row * RB_STRIDE + ko) * 2) = vl;
    }

    // ---- Step 0: h0 = 0 -> h[0] = split(tanh(x_proj[0])) on own tile ------
#pragma unroll
    for (int q = 0; q < 2; q++) {
        int i = tid + q * 256;
        int row = i >> 3, c4 = (i & 7) * 4;
        size_t off = (size_t)(m0 + row) * HH + n0 + c4;
        float4 v = __ldcs(reinterpret_cast<const float4*>(g_xproj + off));
        float o[4] = {tanhf(v.x), tanhf(v.y), tanhf(v.z), tanhf(v.w)};
        *reinterpret_cast<uint2*>(&g_hh[0][off]) =
            make_uint2(pack_hi(o[0], o[1]), pack_hi(o[2], o[3]));
        *reinterpret_cast<uint2*>(&g_hl[0][off]) =
            make_uint2(pack_lo(o[0], o[1]), pack_lo(o[2], o[3]));
    }

    // per-lane ldmatrix addresses
    const int frow = (lane & 7) + ((lane >> 3) & 1) * 8;
    const int fk8  = (lane >> 4) * 8;
    uint32_t a_off[2];
#pragma unroll
    for (int mt = 0; mt < 2; mt++)
        a_off[mt] = (uint32_t)(((wm * 32 + mt * 16 + frow) * RA2_STRIDE + fk8) * 2);
    const int brow = (lane & 7) + (lane >> 4) * 8;
    const int bk8  = ((lane >> 3) & 1) * 8;
    uint32_t b_off[2];
#pragma unroll
    for (int nt = 0; nt < 2; nt++)
        b_off[nt] = (uint32_t)(((nt * 16 + brow) * RB_STRIDE + bk8) * 2);

    const uint32_t ag_base = sb + A2_OFF + wg * A2_GRP;
    const int kg = wg * 256;
    const int gbar = 1 + wg;                // named barrier id for this group

    for (int t = 1; t < TT; t++) {
        __syncthreads();   // prior epilogue reads of XP/red regions complete

        // xp prefetch: issues overlap the barrier spin (commits later, with
        // the first A group of this thread)
        {
            const float* xpt = g_xproj + (size_t)t * BH;
#pragma unroll
            for (int q = 0; q < 2; q++) {
                int i = tid + q * 256;
                int row = i >> 3, c4 = (i & 7) * 4;
                cpa16(sb + XP_OFF + (uint32_t)((row * XP_STRIDE + c4) * 4),
                      xpt + (size_t)(m0 + row) * HH + n0 + c4);
            }
        }

        // band barrier over 32 CTAs: release-add + acquire poll (bounded)
        if (tid == 0) {
            atom_add_release(ctr, 1u);
            unsigned tgt = (unsigned)t * 32u;
            for (int it = 0; it < (1 << 20); ++it) {
                if (ld_acquire(ctr) >= tgt) break;
            }
        }
        __syncthreads();

        const int par = (t - 1) & 1;
        const unsigned short* sh = g_hh[par];
        const unsigned short* sl = g_hl[par];

        float acc[2][4][4];
#pragma unroll
        for (int i = 0; i < 2; i++)
#pragma unroll
            for (int j = 0; j < 4; j++)
#pragma unroll
                for (int q = 0; q < 4; q++) acc[i][j][q] = 0.0f;

        // prologue: stage this group's chunks 0,1
#pragma unroll
        for (int pc = 0; pc < 2; pc++) {
            uint32_t ab = ag_base + pc * A2_BUFSZ;
            int kbase = kg + pc * 32;
#pragma unroll
            for (int j = 0; j < 4; j++) {
                int i = gt + j * 64;
                int row = i >> 2, ko = (i & 3) * 8;
                size_t src = (size_t)(m0 + row) * HH + kbase + ko;
                uint32_t dst = ab + (uint32_t)((row * RA2_STRIDE + ko) * 2);
                cpa16(dst, sh + src);
                cpa16(dst + RA2_SIZE, sl + src);
            }
            CPA_COMMIT();
        }

#pragma unroll 1
        for (int c = 0; c < 8; c++) {
            CPA_WAIT(1);
            BAR_GRP(gbar);

            const uint32_t ab = ag_base + (c & 1) * A2_BUFSZ;
            const uint32_t bkofs = (uint32_t)((kg + c * 32) * 2);
#pragma unroll
            for (int ks = 0; ks < 2; ks++) {
                uint32_t AH[2][4], AL[2][4];
#pragma unroll
                for (int mt = 0; mt < 2; mt++) {
                    ldsm4(AH[mt][0], AH[mt][1], AH[mt][2], AH[mt][3],
                          ab + a_off[mt] + ks * 32);
                    ldsm4(AL[mt][0], AL[mt][1], AL[mt][2], AL[mt][3],
                          ab + RA2_SIZE + a_off[mt] + ks * 32);
                }
#pragma unroll
                for (int nt = 0; nt < 2; nt++) {
                    uint32_t bh0, bh1, bh2, bh3, bl0, bl1, bl2, bl3;
                    ldsm4(bh0, bh1, bh2, bh3, sb + b_off[nt] + bkofs + ks * 32);
                    ldsm4(bl0, bl1, bl2, bl3, sb + RB_SIZE + b_off[nt] + bkofs + ks * 32);
#pragma unroll
                    for (int mt = 0; mt < 2; mt++) {
                        mma16816(acc[mt][nt * 2 + 0], AH[mt][0], AH[mt][1], AH[mt][2], AH[mt][3], bh0, bh1);
                        mma16816(acc[mt][nt * 2 + 1], AH[mt][0], AH[mt][1], AH[mt][2], AH[mt][3], bh2, bh3);
                        mma16816(acc[mt][nt * 2 + 0], AH[mt][0], AH[mt][1], AH[mt][2], AH[mt][3], bl0, bl1);
                        mma16816(acc[mt][nt * 2 + 1], AH[mt][0], AH[mt][1], AH[mt][2], AH[mt][3], bl2, bl3);
                        mma16816(acc[mt][nt * 2 + 0], AL[mt][0], AL[mt][1], AL[mt][2], AL[mt][3], bh0, bh1);
                        mma16816(acc[mt][nt * 2 + 1], AL[mt][0], AL[mt][1], AL[mt][2], AL[mt][3], bh2, bh3);
                    }
                }
            }
            BAR_GRP(gbar);                  // group reads done before restage
            if (c + 2 < 8) {
                uint32_t abn = ag_base + (c & 1) * A2_BUFSZ;
                int kbase = kg + (c + 2) * 32;
#pragma unroll
                for (int j = 0; j < 4; j++) {
                    int i = gt + j * 64;
                    int row = i >> 2, ko = (i & 3) * 8;
                    size_t src = (size_t)(m0 + row) * HH + kbase + ko;
                    uint32_t dst = abn + (uint32_t)((row * RA2_STRIDE + ko) * 2);
                    cpa16(dst, sh + src);
                    cpa16(dst + RA2_SIZE, sl + src);
                }
            }
            CPA_COMMIT();
        }

        // ---- 4-way k-reduction via smem (reuses A2 region) ----------------
        __syncthreads();                     // ALL groups done with A buffers
        {
            float* red = reinterpret_cast<float*>(smem + A2_OFF + wg * RED_GRP);
            const int gid = lane >> 2, tig = lane & 3;
#pragma unroll
            for (int mt = 0; mt < 2; mt++)
#pragma unroll
                for (int half = 0; half < 2; half++) {
                    int row = wm * 32 + mt * 16 + gid + half * 8;
#pragma unroll
                    for (int nq = 0; nq < 4; nq++) {
                        int col = nq * 8 + tig * 2;
                        *reinterpret_cast<float2*>(&red[row * RED_STRIDE + col]) =
                            make_float2(acc[mt][nq][half * 2 + 0],
                                        acc[mt][nq][half * 2 + 1]);
                    }
                }
        }
        __syncthreads();

        // ---- epilogue: sum 4 groups + xp -> tanh -> split -> h (or out) ---
        {
            const int row = tid >> 2;
            const int cb  = (tid & 3) * 8;
            const float* redb = reinterpret_cast<const float*>(smem + A2_OFF);
            float s[8];
            {
                const float* xp = reinterpret_cast<const float*>(
                    smem + XP_OFF) + row * XP_STRIDE + cb;
#pragma unroll
                for (int q = 0; q < 8; q++) s[q] = xp[q];
            }
#pragma unroll
            for (int g = 0; g < 4; g++) {
                const float* r = redb + g * (RED_GRP / 4) + row * RED_STRIDE + cb;
#pragma unroll
                for (int q = 0; q < 8; q++) s[q] += r[q];
            }
            float o[8];
#pragma unroll
            for (int q = 0; q < 8; q++) o[q] = tanhf(s[q]);
            const size_t off = (size_t)(m0 + row) * HH + n0 + cb;
            if (t == TT - 1) {
                for (int cc = 0; cc < copies; cc++) {
                    float4* op = reinterpret_cast<float4*>(out + (size_t)cc * BH + off);
                    op[0] = make_float4(o[0], o[1], o[2], o[3]);
                    op[1] = make_float4(o[4], o[5], o[6], o[7]);
                }
            } else {
                const int wpar = t & 1;
                *reinterpret_cast<uint4*>(&g_hh[wpar][off]) =
                    make_uint4(pack_hi(o[0], o[1]), pack_hi(o[2], o[3]),
                               pack_hi(o[4], o[5]), pack_hi(o[6], o[7]));
                *reinterpret_cast<uint4*>(&g_hl[wpar][off]) =
                    make_uint4(pack_lo(o[0], o[1]), pack_lo(o[2], o[3]),
                               pack_lo(o[4], o[5]), pack_lo(o[6], o[7]));
            }
        }
    }

    // ---- exit: band-local barrier + protected, bounded counter reset ------
    __syncthreads();
    if (tid == 0) {
        atom_add_release(ctr, 1u);
        if (ni == 0) {
            for (int it = 0; it < (1 << 20); ++it) {
                if (ld_acquire(ctr) >= (unsigned)TT * 32u) break;
                __nanosleep(32);
            }
            atomicExch(ctr, 0u);
        }
    }
}

// ---------------------------------------------------------------------------
extern "C" void kernel_launch(void* const* d_in, const int* in_sizes, int n_in,
                              void* d_out, int out_size) {
    const float* xs = nullptr; const float* W = nullptr; const float* b = nullptr;
    for (int i = 0; i < n_in; i++) {
        if (in_sizes[i] == MTOT * DD)            xs = (const float*)d_in[i];
        else if (in_sizes[i] == HH * WSTRIDE)    W  = (const float*)d_in[i];
        else if (in_sizes[i] == HH)              b  = (const float*)d_in[i];
    }
    float* out = (float*)d_out;
    int copies = out_size / BH;
    if (copies < 1) copies = 1;
    if (copies > 2) copies = 2;

    static bool configured = false;
    if (!configured) {
        cudaFuncSetAttribute(xproj_hmma,
                             cudaFuncAttributeMaxDynamicSharedMemorySize, XP2_SMEM);
        cudaFuncSetAttribute(recur_hmma,
                             cudaFuncAttributeMaxDynamicSharedMemorySize, RC_SMEM);
        configured = true;
    }

    xsplit<<<131072, 256>>>(xs);
    w_prep<<<4096, 256>>>(W);
    xproj_hmma<<<dim3(8, 1024), 256, XP2_SMEM>>>(b);
    recur_hmma<<<dim3(32, 4), 256, RC_SMEM>>>(out, copies);
}